// round 1
// baseline (speedup 1.0000x reference)
#include <cuda_runtime.h>
#include <math.h>

// Problem constants
#define BATCH 4
#define NPTS  4096
#define CIN   32
#define KNN   20
#define OUTC  2560

// Scratch (device globals; no allocations allowed)
__device__ float g_sq[BATCH * NPTS];
__device__ float g_scale[1152];
__device__ float g_shift[1152];

// ---------------------------------------------------------------------------
// Kernel 1: per-point squared norms
// ---------------------------------------------------------------------------
__global__ void sqnorm_kernel(const float* __restrict__ x) {
    int i = blockIdx.x * 256 + threadIdx.x;      // 0..16383
    int b = i >> 12, n = i & 4095;
    float s = 0.f;
#pragma unroll
    for (int c = 0; c < CIN; c++) {
        float v = x[(b * CIN + c) * NPTS + n];
        s += v * v;
    }
    g_sq[i] = s;
}

// ---------------------------------------------------------------------------
// Kernel 2: kNN + graph feature max -> writes y (64ch) to 4 concat positions
// Block: 128 threads, 64 rows. Each thread owns 2 rows, scans 1/4 of columns.
// ---------------------------------------------------------------------------
#define KROWS 64

struct ScanSh { float xs[CIN][128]; float sqs[128]; };
struct MergeSh { float mv[KROWS][4][KNN]; int mi[KROWS][4][KNN]; };
union ShU {
    ScanSh s;
    MergeSh m;
    float ytile[64][KROWS];
};

__device__ __forceinline__ void topk_insert(float v, int m, float (&hv)[KNN], int (&hi)[KNN]) {
    if (v > hv[KNN - 1]) {
        hv[KNN - 1] = v; hi[KNN - 1] = m;
#pragma unroll
        for (int j = KNN - 1; j > 0; --j) {
            if (hv[j] > hv[j - 1]) {
                float tv = hv[j]; hv[j] = hv[j - 1]; hv[j - 1] = tv;
                int ti = hi[j]; hi[j] = hi[j - 1]; hi[j - 1] = ti;
            }
        }
    }
}

__global__ void __launch_bounds__(128) knn_kernel(const float* __restrict__ x,
                                                  float* __restrict__ out) {
    __shared__ ShU sh;
    __shared__ int sidx[KROWS][KNN];

    const int tid = threadIdx.x;
    const int b = blockIdx.y;
    const int n0 = blockIdx.x * KROWS;

    const int q = tid & 3;        // column-residue class
    const int rp = tid >> 2;      // 0..31 ; rows rp and rp+32

    const float* Xb = x + b * CIN * NPTS;

    // Row features for my 2 rows
    float xr0[CIN], xr1[CIN];
#pragma unroll
    for (int c = 0; c < CIN; c++) {
        xr0[c] = Xb[c * NPTS + n0 + rp];
        xr1[c] = Xb[c * NPTS + n0 + rp + 32];
    }

    float hv0[KNN], hv1[KNN];
    int hi0[KNN], hi1[KNN];
#pragma unroll
    for (int j = 0; j < KNN; j++) {
        hv0[j] = -3.402823466e38f; hv1[j] = -3.402823466e38f;
        hi0[j] = 0; hi1[j] = 0;
    }

    for (int mt = 0; mt < NPTS / 128; mt++) {
#pragma unroll
        for (int c = 0; c < CIN; c++)
            sh.s.xs[c][tid] = Xb[c * NPTS + mt * 128 + tid];
        sh.s.sqs[tid] = g_sq[b * NPTS + mt * 128 + tid];
        __syncthreads();

#pragma unroll 4
        for (int jj = 0; jj < 32; jj++) {
            int ml = q + 4 * jj;
            float d0 = 0.f, d1 = 0.f;
#pragma unroll
            for (int c = 0; c < CIN; c++) {
                float xv = sh.s.xs[c][ml];
                d0 += xr0[c] * xv;
                d1 += xr1[c] * xv;
            }
            float s2 = sh.s.sqs[ml];
            int mg = mt * 128 + ml;
            topk_insert(2.f * d0 - s2, mg, hv0, hi0);
            topk_insert(2.f * d1 - s2, mg, hv1, hi1);
        }
        __syncthreads();
    }

    // Dump per-thread sorted lists to shared
#pragma unroll
    for (int j = 0; j < KNN; j++) {
        sh.m.mv[rp][q][j] = hv0[j];       sh.m.mi[rp][q][j] = hi0[j];
        sh.m.mv[rp + 32][q][j] = hv1[j];  sh.m.mi[rp + 32][q][j] = hi1[j];
    }
    __syncthreads();

    // 4-way merge per row (threads 0..63), tie-break: larger val, then lower idx
    if (tid < KROWS) {
        int p[4] = {0, 0, 0, 0};
        for (int t = 0; t < KNN; t++) {
            float bv = -3.402823466e38f; int bi = 0x7fffffff; int bq = 0;
#pragma unroll
            for (int qq = 0; qq < 4; qq++) {
                int pp = p[qq];
                float v = sh.m.mv[tid][qq][pp];
                int id = sh.m.mi[tid][qq][pp];
                if (v > bv || (v == bv && id < bi)) { bv = v; bi = id; bq = qq; }
            }
            p[bq]++;
            sidx[tid][t] = bi;
        }
    }
    __syncthreads();

    // Gather neighbors, build y = [max_j(nbr)-x , x]; 2 threads per row, 16 ch each
    {
        int row = tid >> 1;
        int half = tid & 1;
        int n = n0 + row;
#pragma unroll
        for (int cc = 0; cc < 16; cc++) {
            int c = half * 16 + cc;
            const float* xc = Xb + c * NPTS;
            float center = xc[n];
            float mx = -3.402823466e38f;
#pragma unroll
            for (int j = 0; j < KNN; j++)
                mx = fmaxf(mx, xc[sidx[row][j]]);
            sh.ytile[c][row] = mx - center;
            sh.ytile[CIN + c][row] = center;
        }
    }
    __syncthreads();

    // Coalesced writes to the 4 concat positions of y
    for (int i = tid; i < 64 * KROWS; i += 128) {
        int c = i >> 6, rr = i & (KROWS - 1);
        float v = sh.ytile[c][rr];
        int nn = n0 + rr;
        int base = (b * OUTC + c) * NPTS + nn;
        out[base + 0 * NPTS] = v;          // ch 0..63     (y in seg0)
        out[base + 64 * NPTS] = v;         // ch 64..127   (y in y1)
        out[base + 640 * NPTS] = v;        // ch 640..703  (y in y2)
        out[base + 2368 * NPTS] = v;       // ch 2368..2431(y in y3)
    }
}

// ---------------------------------------------------------------------------
// Kernel 3: SGEMM  Z[o,n] = sum_c W[o,c] * Y[c,n] + bias[o]
// 128x128 tile, BK=16, 256 threads, 8x8 microtile (4+4 split).
// Y and Z are channel slices of d_out (row stride NPTS, batch stride OUTC*NPTS)
// ---------------------------------------------------------------------------
__global__ void __launch_bounds__(256) gemm_kernel(
    const float* __restrict__ Wmat, const float* __restrict__ bias,
    float* __restrict__ outp, int inCh0, int outCh0, int C) {
    const int b = blockIdx.z;
    const int n0 = blockIdx.x * 128;
    const int m0 = blockIdx.y * 128;
    const float* Y = outp + (b * OUTC + inCh0) * NPTS;
    float* Z = outp + (b * OUTC + outCh0) * NPTS;

    __shared__ float As[16][132];
    __shared__ float Bs[16][128];

    const int tid = threadIdx.x;
    const int t4 = tid & 3;             // A col group
    const int arow = tid >> 2;          // A row base (0..63)
    const int bk = tid >> 5;            // B k row (0..7)
    const int bn4 = (tid & 31) * 4;     // B n col
    const int tn4 = (tid & 15) * 4;
    const int tm4 = (tid >> 4) * 4;

    float acc[8][8];
#pragma unroll
    for (int i = 0; i < 8; i++)
#pragma unroll
        for (int j = 0; j < 8; j++) acc[i][j] = 0.f;

    for (int kt = 0; kt < C; kt += 16) {
#pragma unroll
        for (int p = 0; p < 2; p++) {
            int row = arow + p * 64;
            float4 w4 = *reinterpret_cast<const float4*>(&Wmat[(m0 + row) * C + kt + t4 * 4]);
            As[t4 * 4 + 0][row] = w4.x;
            As[t4 * 4 + 1][row] = w4.y;
            As[t4 * 4 + 2][row] = w4.z;
            As[t4 * 4 + 3][row] = w4.w;
        }
#pragma unroll
        for (int p = 0; p < 2; p++) {
            int kr = bk + p * 8;
            *reinterpret_cast<float4*>(&Bs[kr][bn4]) =
                *reinterpret_cast<const float4*>(&Y[(kt + kr) * NPTS + n0 + bn4]);
        }
        __syncthreads();

#pragma unroll
        for (int kk = 0; kk < 16; kk++) {
            float a[8], bb[8];
            float4 a0 = *reinterpret_cast<float4*>(&As[kk][tm4]);
            float4 a1 = *reinterpret_cast<float4*>(&As[kk][tm4 + 64]);
            float4 b0 = *reinterpret_cast<float4*>(&Bs[kk][tn4]);
            float4 b1 = *reinterpret_cast<float4*>(&Bs[kk][tn4 + 64]);
            a[0] = a0.x; a[1] = a0.y; a[2] = a0.z; a[3] = a0.w;
            a[4] = a1.x; a[5] = a1.y; a[6] = a1.z; a[7] = a1.w;
            bb[0] = b0.x; bb[1] = b0.y; bb[2] = b0.z; bb[3] = b0.w;
            bb[4] = b1.x; bb[5] = b1.y; bb[6] = b1.z; bb[7] = b1.w;
#pragma unroll
            for (int i = 0; i < 8; i++)
#pragma unroll
                for (int j = 0; j < 8; j++)
                    acc[i][j] += a[i] * bb[j];
        }
        __syncthreads();
    }

#pragma unroll
    for (int i = 0; i < 8; i++) {
        int mrel = (i < 4) ? (tm4 + i) : (64 + tm4 + i - 4);
        float bsv = bias[m0 + mrel];
        float4 v0, v1;
        v0.x = acc[i][0] + bsv; v0.y = acc[i][1] + bsv; v0.z = acc[i][2] + bsv; v0.w = acc[i][3] + bsv;
        v1.x = acc[i][4] + bsv; v1.y = acc[i][5] + bsv; v1.z = acc[i][6] + bsv; v1.w = acc[i][7] + bsv;
        *reinterpret_cast<float4*>(&Z[(m0 + mrel) * NPTS + n0 + tn4]) = v0;
        *reinterpret_cast<float4*>(&Z[(m0 + mrel) * NPTS + n0 + tn4 + 64]) = v1;
    }
}

// ---------------------------------------------------------------------------
// Kernel 4: per-channel batch stats -> scale/shift for BN (one block per ch)
// ---------------------------------------------------------------------------
__global__ void __launch_bounds__(256) stats_kernel(
    const float* __restrict__ outp, int ch0,
    const float* __restrict__ g, const float* __restrict__ be) {
    const int c = blockIdx.x;
    const int tid = threadIdx.x;
    double s = 0.0, s2 = 0.0;
    for (int i = tid; i < BATCH * NPTS; i += 256) {
        int b = i >> 12, n = i & 4095;
        float v = outp[(b * OUTC + ch0 + c) * NPTS + n];
        s += v;
        s2 += (double)v * v;
    }
    __shared__ double rs[256], rs2[256];
    rs[tid] = s; rs2[tid] = s2;
    __syncthreads();
    for (int off = 128; off > 0; off >>= 1) {
        if (tid < off) { rs[tid] += rs[tid + off]; rs2[tid] += rs2[tid + off]; }
        __syncthreads();
    }
    if (tid == 0) {
        double mean = rs[0] / (double)(BATCH * NPTS);
        double var = rs2[0] / (double)(BATCH * NPTS) - mean * mean;
        double inv = 1.0 / sqrt(var + 1e-5);
        float sc = (float)((double)g[c] * inv);
        g_scale[c] = sc;
        g_shift[c] = be[c] - (float)(mean * (double)sc);
    }
}

// ---------------------------------------------------------------------------
// Kernel 5: in-place BN + exact GELU, with up to 2 extra copy destinations
// grid: (NPTS/256, C, BATCH)
// ---------------------------------------------------------------------------
__global__ void __launch_bounds__(256) bn_gelu_kernel(
    float* __restrict__ outp, int ch0, int dst1, int dst2) {
    const int n = blockIdx.x * 256 + threadIdx.x;
    const int c = blockIdx.y;
    const int b = blockIdx.z;
    const float sc = g_scale[c];
    const float sf = g_shift[c];
    int base = (b * OUTC + ch0 + c) * NPTS + n;
    float z = outp[base];
    float zn = z * sc + sf;
    float a = 0.5f * zn * (1.f + erff(zn * 0.70710678118654752f));
    outp[base] = a;
    if (dst1 >= 0) outp[(b * OUTC + dst1 + c) * NPTS + n] = a;
    if (dst2 >= 0) outp[(b * OUTC + dst2 + c) * NPTS + n] = a;
}

// ---------------------------------------------------------------------------
// Launch: all intermediates live directly in d_out.
// out channel map: y[0,64) y[64,128) a1[128,256) a2[256,640) y[640,704)
//                  a1[704,832) a3[832,1984) a2[1984,2368) y[2368,2432) a1[2432,2560)
// y1 = ch[64,256) contiguous; y2 = ch[256,832) contiguous.
// ---------------------------------------------------------------------------
extern "C" void kernel_launch(void* const* d_in, const int* in_sizes, int n_in,
                              void* d_out, int out_size) {
    const float* x  = (const float*)d_in[0];
    const float* W1 = (const float*)d_in[1];
    const float* b1 = (const float*)d_in[2];
    const float* g1 = (const float*)d_in[3];
    const float* be1 = (const float*)d_in[4];
    const float* W2 = (const float*)d_in[5];
    const float* b2 = (const float*)d_in[6];
    const float* g2 = (const float*)d_in[7];
    const float* be2 = (const float*)d_in[8];
    const float* W3 = (const float*)d_in[9];
    const float* b3 = (const float*)d_in[10];
    const float* g3 = (const float*)d_in[11];
    const float* be3 = (const float*)d_in[12];
    float* out = (float*)d_out;

    sqnorm_kernel<<<BATCH * NPTS / 256, 256>>>(x);
    knn_kernel<<<dim3(NPTS / KROWS, BATCH), 128>>>(x, out);

    // Stage 1: z1 = W1 @ y  (in ch[0,64) -> out ch[128,256)), O=128, C=64
    gemm_kernel<<<dim3(NPTS / 128, 1, BATCH), 256>>>(W1, b1, out, 0, 128, 64);
    stats_kernel<<<128, 256>>>(out, 128, g1, be1);
    bn_gelu_kernel<<<dim3(NPTS / 256, 128, BATCH), 256>>>(out, 128, 704, 2432);

    // Stage 2: z2 = W2 @ y1 (in ch[64,256) -> out ch[256,640)), O=384, C=192
    gemm_kernel<<<dim3(NPTS / 128, 3, BATCH), 256>>>(W2, b2, out, 64, 256, 192);
    stats_kernel<<<384, 256>>>(out, 256, g2, be2);
    bn_gelu_kernel<<<dim3(NPTS / 256, 384, BATCH), 256>>>(out, 256, 1984, -1);

    // Stage 3: z3 = W3 @ y2 (in ch[256,832) -> out ch[832,1984)), O=1152, C=576
    gemm_kernel<<<dim3(NPTS / 128, 9, BATCH), 256>>>(W3, b3, out, 256, 832, 576);
    stats_kernel<<<1152, 256>>>(out, 832, g3, be3);
    bn_gelu_kernel<<<dim3(NPTS / 256, 1152, BATCH), 256>>>(out, 832, -1, -1);
}

// round 5
// speedup vs baseline: 1.2184x; 1.2184x over previous
#include <cuda_runtime.h>
#include <cuda_bf16.h>
#include <math.h>
#include <stdint.h>

// Problem constants
#define BATCH 4
#define NPTS  4096
#define CIN   32
#define KNN   20
#define OUTC  2560
#define PTOT  16384   // BATCH * NPTS

// ---------------------------------------------------------------------------
// Scratch (device globals; no allocations allowed)
// ---------------------------------------------------------------------------
__device__ float g_sq[BATCH * NPTS];
__device__ float g_scale[1152];
__device__ float g_shift[1152];

// bf16-split operand scratch
__device__ __align__(256) __nv_bfloat16 g_yh[576 * PTOT];
__device__ __align__(256) __nv_bfloat16 g_yl[576 * PTOT];
__device__ __align__(256) __nv_bfloat16 g_w2h[384 * 192];
__device__ __align__(256) __nv_bfloat16 g_w2l[384 * 192];
__device__ __align__(256) __nv_bfloat16 g_w3h[1152 * 576];
__device__ __align__(256) __nv_bfloat16 g_w3l[1152 * 576];

// ---------------------------------------------------------------------------
// Asm helpers (all sm_80+ ISA; compiles for base sm_100)
// ---------------------------------------------------------------------------
__device__ __forceinline__ uint32_t smem_to_u32(const void* p) {
    uint32_t a;
    asm("{ .reg .u64 t; cvta.to.shared.u64 t, %1; cvt.u32.u64 %0, t; }" : "=r"(a) : "l"(p));
    return a;
}
__device__ __forceinline__ void cp_async16(uint32_t dst, const void* src) {
    asm volatile("cp.async.cg.shared.global [%0], [%1], 16;" :: "r"(dst), "l"(src));
}
#define CP_COMMIT() asm volatile("cp.async.commit_group;" ::: "memory")
#define CP_WAIT(n)  asm volatile("cp.async.wait_group %0;" :: "n"(n) : "memory")

__device__ __forceinline__ void ldsm_x4(uint32_t (&r)[4], uint32_t a) {
    asm volatile("ldmatrix.sync.aligned.m8n8.x4.shared.b16 {%0,%1,%2,%3}, [%4];"
        : "=r"(r[0]), "=r"(r[1]), "=r"(r[2]), "=r"(r[3]) : "r"(a));
}
__device__ __forceinline__ void ldsm_x4_t(uint32_t (&r)[4], uint32_t a) {
    asm volatile("ldmatrix.sync.aligned.m8n8.x4.trans.shared.b16 {%0,%1,%2,%3}, [%4];"
        : "=r"(r[0]), "=r"(r[1]), "=r"(r[2]), "=r"(r[3]) : "r"(a));
}
__device__ __forceinline__ void mma_bf16(float (&d)[4], const uint32_t (&a)[4],
                                         uint32_t b0, uint32_t b1) {
    asm volatile(
        "mma.sync.aligned.m16n8k16.row.col.f32.bf16.bf16.f32 "
        "{%0,%1,%2,%3},{%4,%5,%6,%7},{%8,%9},{%0,%1,%2,%3};"
        : "+f"(d[0]), "+f"(d[1]), "+f"(d[2]), "+f"(d[3])
        : "r"(a[0]), "r"(a[1]), "r"(a[2]), "r"(a[3]), "r"(b0), "r"(b1));
}

// ---------------------------------------------------------------------------
// Kernel 1: per-point squared norms
// ---------------------------------------------------------------------------
__global__ void sqnorm_kernel(const float* __restrict__ x) {
    int i = blockIdx.x * 256 + threadIdx.x;
    int b = i >> 12, n = i & 4095;
    float s = 0.f;
#pragma unroll
    for (int c = 0; c < CIN; c++) {
        float v = x[(b * CIN + c) * NPTS + n];
        s += v * v;
    }
    g_sq[i] = s;
}

// ---------------------------------------------------------------------------
// Kernel 2: kNN + graph feature max (validated in R1)
// ---------------------------------------------------------------------------
#define KROWS 64
struct ScanSh { float xs[CIN][128]; float sqs[128]; };
struct MergeSh { float mv[KROWS][4][KNN]; int mi[KROWS][4][KNN]; };
union ShU { ScanSh s; MergeSh m; float ytile[64][KROWS]; };

__device__ __forceinline__ void topk_insert(float v, int m, float (&hv)[KNN], int (&hi)[KNN]) {
    if (v > hv[KNN - 1]) {
        hv[KNN - 1] = v; hi[KNN - 1] = m;
#pragma unroll
        for (int j = KNN - 1; j > 0; --j) {
            if (hv[j] > hv[j - 1]) {
                float tv = hv[j]; hv[j] = hv[j - 1]; hv[j - 1] = tv;
                int ti = hi[j]; hi[j] = hi[j - 1]; hi[j - 1] = ti;
            }
        }
    }
}

__global__ void __launch_bounds__(128) knn_kernel(const float* __restrict__ x,
                                                  float* __restrict__ out) {
    __shared__ ShU sh;
    __shared__ int sidx[KROWS][KNN];
    const int tid = threadIdx.x;
    const int b = blockIdx.y;
    const int n0 = blockIdx.x * KROWS;
    const int q = tid & 3;
    const int rp = tid >> 2;
    const float* Xb = x + b * CIN * NPTS;

    float xr0[CIN], xr1[CIN];
#pragma unroll
    for (int c = 0; c < CIN; c++) {
        xr0[c] = Xb[c * NPTS + n0 + rp];
        xr1[c] = Xb[c * NPTS + n0 + rp + 32];
    }
    float hv0[KNN], hv1[KNN];
    int hi0[KNN], hi1[KNN];
#pragma unroll
    for (int j = 0; j < KNN; j++) {
        hv0[j] = -3.402823466e38f; hv1[j] = -3.402823466e38f;
        hi0[j] = 0; hi1[j] = 0;
    }
    for (int mt = 0; mt < NPTS / 128; mt++) {
#pragma unroll
        for (int c = 0; c < CIN; c++)
            sh.s.xs[c][tid] = Xb[c * NPTS + mt * 128 + tid];
        sh.s.sqs[tid] = g_sq[b * NPTS + mt * 128 + tid];
        __syncthreads();
#pragma unroll 4
        for (int jj = 0; jj < 32; jj++) {
            int ml = q + 4 * jj;
            float d0 = 0.f, d1 = 0.f;
#pragma unroll
            for (int c = 0; c < CIN; c++) {
                float xv = sh.s.xs[c][ml];
                d0 += xr0[c] * xv;
                d1 += xr1[c] * xv;
            }
            float s2 = sh.s.sqs[ml];
            int mg = mt * 128 + ml;
            topk_insert(2.f * d0 - s2, mg, hv0, hi0);
            topk_insert(2.f * d1 - s2, mg, hv1, hi1);
        }
        __syncthreads();
    }
#pragma unroll
    for (int j = 0; j < KNN; j++) {
        sh.m.mv[rp][q][j] = hv0[j];       sh.m.mi[rp][q][j] = hi0[j];
        sh.m.mv[rp + 32][q][j] = hv1[j];  sh.m.mi[rp + 32][q][j] = hi1[j];
    }
    __syncthreads();
    if (tid < KROWS) {
        int p[4] = {0, 0, 0, 0};
        for (int t = 0; t < KNN; t++) {
            float bv = -3.402823466e38f; int bi = 0x7fffffff; int bq = 0;
#pragma unroll
            for (int qq = 0; qq < 4; qq++) {
                int pp = p[qq];
                float v = sh.m.mv[tid][qq][pp];
                int id = sh.m.mi[tid][qq][pp];
                if (v > bv || (v == bv && id < bi)) { bv = v; bi = id; bq = qq; }
            }
            p[bq]++;
            sidx[tid][t] = bi;
        }
    }
    __syncthreads();
    {
        int row = tid >> 1;
        int half = tid & 1;
        int n = n0 + row;
#pragma unroll
        for (int cc = 0; cc < 16; cc++) {
            int c = half * 16 + cc;
            const float* xc = Xb + c * NPTS;
            float center = xc[n];
            float mx = -3.402823466e38f;
#pragma unroll
            for (int j = 0; j < KNN; j++)
                mx = fmaxf(mx, xc[sidx[row][j]]);
            sh.ytile[c][row] = mx - center;
            sh.ytile[CIN + c][row] = center;
        }
    }
    __syncthreads();
    for (int i = tid; i < 64 * KROWS; i += 128) {
        int c = i >> 6, rr = i & (KROWS - 1);
        float v = sh.ytile[c][rr];
        int nn = n0 + rr;
        int base = (b * OUTC + c) * NPTS + nn;
        out[base + 0 * NPTS] = v;
        out[base + 64 * NPTS] = v;
        out[base + 640 * NPTS] = v;
        out[base + 2368 * NPTS] = v;
    }
}

// ---------------------------------------------------------------------------
// Kernel 3: FFMA SGEMM (only GEMM1: 128x64x16384, tiny)
// ---------------------------------------------------------------------------
__global__ void __launch_bounds__(256) gemm_kernel(
    const float* __restrict__ Wmat, const float* __restrict__ bias,
    float* __restrict__ outp, int inCh0, int outCh0, int C) {
    const int b = blockIdx.z;
    const int n0 = blockIdx.x * 128;
    const int m0 = blockIdx.y * 128;
    const float* Y = outp + (b * OUTC + inCh0) * NPTS;
    float* Z = outp + (b * OUTC + outCh0) * NPTS;
    __shared__ float As[16][132];
    __shared__ float Bs[16][128];
    const int tid = threadIdx.x;
    const int t4 = tid & 3;
    const int arow = tid >> 2;
    const int bk = tid >> 5;
    const int bn4 = (tid & 31) * 4;
    const int tn4 = (tid & 15) * 4;
    const int tm4 = (tid >> 4) * 4;
    float acc[8][8];
#pragma unroll
    for (int i = 0; i < 8; i++)
#pragma unroll
        for (int j = 0; j < 8; j++) acc[i][j] = 0.f;
    for (int kt = 0; kt < C; kt += 16) {
#pragma unroll
        for (int p = 0; p < 2; p++) {
            int row = arow + p * 64;
            float4 w4 = *reinterpret_cast<const float4*>(&Wmat[(m0 + row) * C + kt + t4 * 4]);
            As[t4 * 4 + 0][row] = w4.x;
            As[t4 * 4 + 1][row] = w4.y;
            As[t4 * 4 + 2][row] = w4.z;
            As[t4 * 4 + 3][row] = w4.w;
        }
#pragma unroll
        for (int p = 0; p < 2; p++) {
            int kr = bk + p * 8;
            *reinterpret_cast<float4*>(&Bs[kr][bn4]) =
                *reinterpret_cast<const float4*>(&Y[(kt + kr) * NPTS + n0 + bn4]);
        }
        __syncthreads();
#pragma unroll
        for (int kk = 0; kk < 16; kk++) {
            float a[8], bb[8];
            float4 a0 = *reinterpret_cast<float4*>(&As[kk][tm4]);
            float4 a1 = *reinterpret_cast<float4*>(&As[kk][tm4 + 64]);
            float4 b0 = *reinterpret_cast<float4*>(&Bs[kk][tn4]);
            float4 b1 = *reinterpret_cast<float4*>(&Bs[kk][tn4 + 64]);
            a[0] = a0.x; a[1] = a0.y; a[2] = a0.z; a[3] = a0.w;
            a[4] = a1.x; a[5] = a1.y; a[6] = a1.z; a[7] = a1.w;
            bb[0] = b0.x; bb[1] = b0.y; bb[2] = b0.z; bb[3] = b0.w;
            bb[4] = b1.x; bb[5] = b1.y; bb[6] = b1.z; bb[7] = b1.w;
#pragma unroll
            for (int i = 0; i < 8; i++)
#pragma unroll
                for (int j = 0; j < 8; j++)
                    acc[i][j] += a[i] * bb[j];
        }
        __syncthreads();
    }
#pragma unroll
    for (int i = 0; i < 8; i++) {
        int mrel = (i < 4) ? (tm4 + i) : (64 + tm4 + i - 4);
        float bsv = bias[m0 + mrel];
        float4 v0, v1;
        v0.x = acc[i][0] + bsv; v0.y = acc[i][1] + bsv; v0.z = acc[i][2] + bsv; v0.w = acc[i][3] + bsv;
        v1.x = acc[i][4] + bsv; v1.y = acc[i][5] + bsv; v1.z = acc[i][6] + bsv; v1.w = acc[i][7] + bsv;
        *reinterpret_cast<float4*>(&Z[(m0 + mrel) * NPTS + n0 + tn4]) = v0;
        *reinterpret_cast<float4*>(&Z[(m0 + mrel) * NPTS + n0 + tn4 + 64]) = v1;
    }
}

// ---------------------------------------------------------------------------
// Kernel 4/5: batch stats + BN/GELU (validated in R1)
// ---------------------------------------------------------------------------
__global__ void __launch_bounds__(256) stats_kernel(
    const float* __restrict__ outp, int ch0,
    const float* __restrict__ g, const float* __restrict__ be) {
    const int c = blockIdx.x;
    const int tid = threadIdx.x;
    double s = 0.0, s2 = 0.0;
    for (int i = tid; i < BATCH * NPTS; i += 256) {
        int b = i >> 12, n = i & 4095;
        float v = outp[(b * OUTC + ch0 + c) * NPTS + n];
        s += v;
        s2 += (double)v * v;
    }
    __shared__ double rs[256], rs2[256];
    rs[tid] = s; rs2[tid] = s2;
    __syncthreads();
    for (int off = 128; off > 0; off >>= 1) {
        if (tid < off) { rs[tid] += rs[tid + off]; rs2[tid] += rs2[tid + off]; }
        __syncthreads();
    }
    if (tid == 0) {
        double mean = rs[0] / (double)(BATCH * NPTS);
        double var = rs2[0] / (double)(BATCH * NPTS) - mean * mean;
        double inv = 1.0 / sqrt(var + 1e-5);
        float sc = (float)((double)g[c] * inv);
        g_scale[c] = sc;
        g_shift[c] = be[c] - (float)(mean * (double)sc);
    }
}

__global__ void __launch_bounds__(256) bn_gelu_kernel(
    float* __restrict__ outp, int ch0, int dst1, int dst2) {
    const int n = blockIdx.x * 256 + threadIdx.x;
    const int c = blockIdx.y;
    const int b = blockIdx.z;
    const float sc = g_scale[c];
    const float sf = g_shift[c];
    int base = (b * OUTC + ch0 + c) * NPTS + n;
    float z = outp[base];
    float zn = z * sc + sf;
    float a = 0.5f * zn * (1.f + erff(zn * 0.70710678118654752f));
    outp[base] = a;
    if (dst1 >= 0) outp[(b * OUTC + dst1 + c) * NPTS + n] = a;
    if (dst2 >= 0) outp[(b * OUTC + dst2 + c) * NPTS + n] = a;
}

// ---------------------------------------------------------------------------
// Kernel 6: weight split fp32 -> bf16 hi/lo (layout preserved [M][K])
// ---------------------------------------------------------------------------
__global__ void splitw_kernel(const float* __restrict__ W,
                              __nv_bfloat16* __restrict__ hi,
                              __nv_bfloat16* __restrict__ lo, int n) {
    int i = blockIdx.x * 256 + threadIdx.x;
    if (i < n) {
        float v = W[i];
        __nv_bfloat16 h = __float2bfloat16(v);
        hi[i] = h;
        lo[i] = __float2bfloat16(v - __bfloat162float(h));
    }
}

// ---------------------------------------------------------------------------
// Kernel 7: activation split: out[b][ch0+c][n] -> Y[c][b*4096+n] bf16 hi/lo
// (no transpose needed: mma.sync B operand is K-major = channel-major)
// ---------------------------------------------------------------------------
__global__ void __launch_bounds__(256) splity_kernel(
    const float* __restrict__ outp, int ch0,
    __nv_bfloat16* __restrict__ hi, __nv_bfloat16* __restrict__ lo) {
    int n = blockIdx.x * 256 + threadIdx.x;
    int c = blockIdx.y;
    int b = blockIdx.z;
    float v = outp[((size_t)b * OUTC + ch0 + c) * NPTS + n];
    __nv_bfloat16 h = __float2bfloat16(v);
    int o = c * PTOT + b * 4096 + n;
    hi[o] = h;
    lo[o] = __float2bfloat16(v - __bfloat162float(h));
}

// ---------------------------------------------------------------------------
// Kernel 8: bf16x3 mma.sync GEMM.  Z[M, 16384] = W[M,K] * Y[K,16384] + bias
// 128x128x32 threadblock, 8 warps (4m x 2n), 32x64 warp tile, m16n8k16.
// cp.async double buffer; ldmatrix (trans for B).
// ---------------------------------------------------------------------------
#define ASTR 40      // A smem row stride (elements): 32 + 8 pad
#define BSTR 136     // B smem row stride (elements): 128 + 8 pad
#define A_H  0
#define A_L  5120    // 128*40
#define B_H  10240
#define B_L  14592   // 10240 + 32*136
#define STAGE_E 18944
#define GSMEM_BYTES (2 * STAGE_E * 2)   // 75776

__device__ __forceinline__ void mg_load_stage(
    uint32_t sb, int buf, int kt, int m0, int n0,
    const __nv_bfloat16* Wh, const __nv_bfloat16* Wl,
    const __nv_bfloat16* Yh, const __nv_bfloat16* Yl, int K, int tid) {
    uint32_t st = sb + buf * STAGE_E * 2;
#pragma unroll
    for (int h = 0; h < 2; h++) {
        int ci = tid + h * 256;
        // A chunk: 128 rows x 4 x 16B
        int r = ci >> 2, c8 = (ci & 3) * 8;
        uint32_t d = st + (A_H + r * ASTR + c8) * 2;
        size_t g = (size_t)(m0 + r) * K + kt + c8;
        cp_async16(d, Wh + g);
        cp_async16(d + (A_L - A_H) * 2, Wl + g);
        // B chunk: 32 rows x 16 x 16B
        int rb = ci >> 4, cb8 = (ci & 15) * 8;
        uint32_t db = st + (B_H + rb * BSTR + cb8) * 2;
        size_t gb = (size_t)(kt + rb) * PTOT + n0 + cb8;
        cp_async16(db, Yh + gb);
        cp_async16(db + (B_L - B_H) * 2, Yl + gb);
    }
}

__global__ void __launch_bounds__(256, 1) mma_gemm(
    const __nv_bfloat16* __restrict__ Wh, const __nv_bfloat16* __restrict__ Wl,
    const __nv_bfloat16* __restrict__ Yh, const __nv_bfloat16* __restrict__ Yl,
    const float* __restrict__ bias, float* __restrict__ outp,
    int outCh0, int K) {
    extern __shared__ char smem[];
    uint32_t sb = smem_to_u32(smem);
    const int tid = threadIdx.x;
    const int lane = tid & 31;
    const int warp = tid >> 5;
    const int wm = warp >> 1;         // 0..3
    const int wn = warp & 1;          // 0..1
    const int n0 = blockIdx.x * 128;
    const int m0 = blockIdx.y * 128;
    const int lrow8 = ((lane >> 3) & 1) * 8 + (lane & 7);
    const int lcol8 = (lane >> 4) * 8;

    float acc[2][8][4];
#pragma unroll
    for (int mt = 0; mt < 2; mt++)
#pragma unroll
        for (int nt = 0; nt < 8; nt++)
#pragma unroll
            for (int k = 0; k < 4; k++) acc[mt][nt][k] = 0.f;

    const int niter = K / 32;
    mg_load_stage(sb, 0, 0, m0, n0, Wh, Wl, Yh, Yl, K, tid);
    CP_COMMIT();

    for (int it = 0; it < niter; it++) {
        int buf = it & 1;
        if (it + 1 < niter) {
            mg_load_stage(sb, buf ^ 1, (it + 1) * 32, m0, n0, Wh, Wl, Yh, Yl, K, tid);
            CP_COMMIT();
            CP_WAIT(1);
        } else {
            CP_WAIT(0);
        }
        __syncthreads();

        uint32_t st = sb + buf * STAGE_E * 2;
#pragma unroll
        for (int s = 0; s < 32; s += 16) {
            uint32_t ah[2][4], al[2][4];
#pragma unroll
            for (int mt = 0; mt < 2; mt++) {
                uint32_t off = (uint32_t)((wm * 32 + mt * 16 + lrow8) * ASTR + s + lcol8);
                ldsm_x4(ah[mt], st + (A_H + off) * 2);
                ldsm_x4(al[mt], st + (A_L + off) * 2);
            }
            uint32_t bh[4][4], bl[4][4];
#pragma unroll
            for (int g4 = 0; g4 < 4; g4++) {
                uint32_t off = (uint32_t)((s + lrow8) * BSTR + wn * 64 + g4 * 16 + lcol8);
                ldsm_x4_t(bh[g4], st + (B_H + off) * 2);
                ldsm_x4_t(bl[g4], st + (B_L + off) * 2);
            }
#pragma unroll
            for (int mt = 0; mt < 2; mt++)
#pragma unroll
                for (int nt = 0; nt < 8; nt++) {
                    int g4 = nt >> 1, pq = (nt & 1) * 2;
                    mma_bf16(acc[mt][nt], ah[mt], bh[g4][pq], bh[g4][pq + 1]);
                    mma_bf16(acc[mt][nt], ah[mt], bl[g4][pq], bl[g4][pq + 1]);
                    mma_bf16(acc[mt][nt], al[mt], bh[g4][pq], bh[g4][pq + 1]);
                }
        }
        __syncthreads();
    }

    // Epilogue: write Z = acc + bias into d_out channel slice
    const int g = lane >> 2, tig = lane & 3;
    const int b = n0 >> 12;
    const int nnbase = (n0 & 4095) + wn * 64 + 2 * tig;
#pragma unroll
    for (int mt = 0; mt < 2; mt++) {
        int mrow = m0 + wm * 32 + mt * 16 + g;
        float bv0 = bias[mrow];
        float bv1 = bias[mrow + 8];
        float* z0 = outp + ((size_t)(b * OUTC + outCh0 + mrow)) * 4096;
        float* z1 = z0 + 8 * 4096;
#pragma unroll
        for (int nt = 0; nt < 8; nt++) {
            int nn = nnbase + nt * 8;
            float2 v0 = make_float2(acc[mt][nt][0] + bv0, acc[mt][nt][1] + bv0);
            float2 v1 = make_float2(acc[mt][nt][2] + bv1, acc[mt][nt][3] + bv1);
            *reinterpret_cast<float2*>(&z0[nn]) = v0;
            *reinterpret_cast<float2*>(&z1[nn]) = v1;
        }
    }
}

// ---------------------------------------------------------------------------
// Host launch sequence
// ---------------------------------------------------------------------------
extern "C" void kernel_launch(void* const* d_in, const int* in_sizes, int n_in,
                              void* d_out, int out_size) {
    const float* x   = (const float*)d_in[0];
    const float* W1  = (const float*)d_in[1];
    const float* b1  = (const float*)d_in[2];
    const float* g1  = (const float*)d_in[3];
    const float* be1 = (const float*)d_in[4];
    const float* W2  = (const float*)d_in[5];
    const float* b2  = (const float*)d_in[6];
    const float* g2  = (const float*)d_in[7];
    const float* be2 = (const float*)d_in[8];
    const float* W3  = (const float*)d_in[9];
    const float* b3  = (const float*)d_in[10];
    const float* g3  = (const float*)d_in[11];
    const float* be3 = (const float*)d_in[12];
    float* out = (float*)d_out;

    void *p_yh, *p_yl, *p_w2h, *p_w2l, *p_w3h, *p_w3l;
    cudaGetSymbolAddress(&p_yh, g_yh);   cudaGetSymbolAddress(&p_yl, g_yl);
    cudaGetSymbolAddress(&p_w2h, g_w2h); cudaGetSymbolAddress(&p_w2l, g_w2l);
    cudaGetSymbolAddress(&p_w3h, g_w3h); cudaGetSymbolAddress(&p_w3l, g_w3l);

    cudaFuncSetAttribute(mma_gemm, cudaFuncAttributeMaxDynamicSharedMemorySize,
                         GSMEM_BYTES);

    // Weight splits (independent of data path)
    splitw_kernel<<<(384 * 192 + 255) / 256, 256>>>(W2, (__nv_bfloat16*)p_w2h,
                                                    (__nv_bfloat16*)p_w2l, 384 * 192);
    splitw_kernel<<<(1152 * 576 + 255) / 256, 256>>>(W3, (__nv_bfloat16*)p_w3h,
                                                     (__nv_bfloat16*)p_w3l, 1152 * 576);

    sqnorm_kernel<<<BATCH * NPTS / 256, 256>>>(x);
    knn_kernel<<<dim3(NPTS / KROWS, BATCH), 128>>>(x, out);

    // Stage 1 (FFMA): z1 = W1 @ y -> ch[128,256), O=128, C=64
    gemm_kernel<<<dim3(NPTS / 128, 1, BATCH), 256>>>(W1, b1, out, 0, 128, 64);
    stats_kernel<<<128, 256>>>(out, 128, g1, be1);
    bn_gelu_kernel<<<dim3(NPTS / 256, 128, BATCH), 256>>>(out, 128, 704, 2432);

    // Stage 2 (bf16x3 mma): input y1 = ch[64,256), O=384, C=192 -> ch[256,640)
    splity_kernel<<<dim3(16, 192, 4), 256>>>(out, 64, (__nv_bfloat16*)p_yh,
                                             (__nv_bfloat16*)p_yl);
    mma_gemm<<<dim3(128, 3), 256, GSMEM_BYTES>>>(
        (const __nv_bfloat16*)p_w2h, (const __nv_bfloat16*)p_w2l,
        (const __nv_bfloat16*)p_yh, (const __nv_bfloat16*)p_yl, b2, out, 256, 192);
    stats_kernel<<<384, 256>>>(out, 256, g2, be2);
    bn_gelu_kernel<<<dim3(NPTS / 256, 384, BATCH), 256>>>(out, 256, 1984, -1);

    // Stage 3 (bf16x3 mma): input y2 = ch[256,832), O=1152, C=576 -> ch[832,1984)
    splity_kernel<<<dim3(16, 576, 4), 256>>>(out, 256, (__nv_bfloat16*)p_yh,
                                             (__nv_bfloat16*)p_yl);
    mma_gemm<<<dim3(128, 9), 256, GSMEM_BYTES>>>(
        (const __nv_bfloat16*)p_w3h, (const __nv_bfloat16*)p_w3l,
        (const __nv_bfloat16*)p_yh, (const __nv_bfloat16*)p_yl, b3, out, 832, 576);
    stats_kernel<<<1152, 256>>>(out, 832, g3, be3);
    bn_gelu_kernel<<<dim3(NPTS / 256, 1152, BATCH), 256>>>(out, 832, -1, -1);
}